// round 2
// baseline (speedup 1.0000x reference)
#include <cuda_runtime.h>
#include <math.h>

#define BB 4096
#define LL 32
#define DD 300
#define HH 6
#define HDD 50
#define NT 320   // 10 warps

// Transposed weight scratch: WqT, WkT, WvT, WoT, VaT  (k-major: WT[k*D+d] = W[d*D+k])
__device__ float g_WT[5][DD * DD];

__global__ void transpose_kernel(const float* __restrict__ Wq,
                                 const float* __restrict__ Wk,
                                 const float* __restrict__ Wv,
                                 const float* __restrict__ Wo,
                                 const float* __restrict__ Va) {
    const float* src;
    int m = blockIdx.y;
    switch (m) {
        case 0: src = Wq; break;
        case 1: src = Wk; break;
        case 2: src = Wv; break;
        case 3: src = Wo; break;
        default: src = Va; break;
    }
    float* dst = g_WT[m];
    for (int idx = blockIdx.x * blockDim.x + threadIdx.x; idx < DD * DD;
         idx += gridDim.x * blockDim.x) {
        int k = idx / DD;
        int d = idx - k * DD;
        dst[idx] = src[d * DD + k];   // coalesced write, strided read (tiny, once)
    }
}

__global__ __launch_bounds__(NT, 1)
void encoder_kernel(const int* __restrict__ title,
                    const float* __restrict__ emb,
                    const float* __restrict__ pos,
                    const float* __restrict__ bq,
                    const float* __restrict__ bk,
                    const float* __restrict__ bv,
                    const float* __restrict__ bo,
                    const float* __restrict__ ba,
                    const float* __restrict__ qw,
                    float* __restrict__ out) {
    extern __shared__ float sm[];
    float* SX  = sm;                 // [32][300]  x, later ctx
    float* SQ  = sm + 1 * LL * DD;   // [32][300]  q, later ctx2
    float* SK  = sm + 2 * LL * DD;   // [32][300]  k, later t=tanh(...)
    float* SV  = sm + 3 * LL * DD;   // [32][300]  v
    float* SA  = sm + 4 * LL * DD;   // [32] raw pooling scores
    float* SAL = SA + 32;            // [32] alpha
    int*   STL = (int*)(SAL + 32);   // [32] tokens

    const int b   = blockIdx.x;
    const int tid = threadIdx.x;

    if (tid < LL) STL[tid] = title[b * LL + tid];
    __syncthreads();

    // ---------------- Phase A: x = emb[title] + pos ----------------
    for (int idx = tid; idx < LL * DD; idx += NT) {
        int l = idx / DD;
        int d = idx - l * DD;
        SX[idx] = emb[(size_t)STL[l] * DD + d] + pos[idx];
    }
    __syncthreads();

    // ---------------- Phase B: q,k,v (fused 3 GEMMs) ----------------
    const float* WqT = g_WT[0];
    const float* WkT = g_WT[1];
    const float* WvT = g_WT[2];
    if (tid < DD) {
        const int d = tid;
        const float bbq = bq[d], bbk = bk[d], bbv = bv[d];
        const float rs = rsqrtf((float)HDD);
        for (int lh = 0; lh < 2; ++lh) {
            float aq[16], ak[16], av[16];
            #pragma unroll
            for (int u = 0; u < 16; ++u) { aq[u] = 0.f; ak[u] = 0.f; av[u] = 0.f; }
            const float* xb = SX + lh * 16 * DD;
            #pragma unroll 4
            for (int kk = 0; kk < DD; ++kk) {
                float wq = WqT[kk * DD + d];
                float wk = WkT[kk * DD + d];
                float wv = WvT[kk * DD + d];
                #pragma unroll
                for (int u = 0; u < 16; ++u) {
                    float xv = xb[u * DD + kk];   // LDS broadcast
                    aq[u] = fmaf(xv, wq, aq[u]);
                    ak[u] = fmaf(xv, wk, ak[u]);
                    av[u] = fmaf(xv, wv, av[u]);
                }
            }
            #pragma unroll
            for (int u = 0; u < 16; ++u) {
                int l = lh * 16 + u;
                SQ[l * DD + d] = (aq[u] + bbq) * rs;
                SK[l * DD + d] = ak[u] + bbk;
                SV[l * DD + d] = av[u] + bbv;
            }
        }
    }
    __syncthreads();

    // ---------------- Phase C: attention, ctx -> SX ----------------
    if (tid < HH * LL) {
        const int h = tid >> 5;       // warp == head
        const int i = tid & 31;       // lane == query row
        const int off = h * HDD;
        float s[LL];
        #pragma unroll
        for (int j = 0; j < LL; ++j) s[j] = 0.f;
        for (int hd = 0; hd < HDD; ++hd) {
            float qv = SQ[i * DD + off + hd];
            #pragma unroll
            for (int j = 0; j < LL; ++j)
                s[j] = fmaf(qv, SK[j * DD + off + hd], s[j]);   // k: LDS broadcast
        }
        float m = -1e30f;
        #pragma unroll
        for (int j = 0; j < LL; ++j) m = fmaxf(m, s[j]);
        float sum = 0.f;
        #pragma unroll
        for (int j = 0; j < LL; ++j) { s[j] = __expf(s[j] - m); sum += s[j]; }
        float inv = 1.f / sum;
        #pragma unroll
        for (int j = 0; j < LL; ++j) s[j] *= inv;
        for (int hd = 0; hd < HDD; ++hd) {
            float c = 0.f;
            #pragma unroll
            for (int j = 0; j < LL; ++j)
                c = fmaf(s[j], SV[j * DD + off + hd], c);       // v: LDS broadcast
            SX[i * DD + off + hd] = c;
        }
    }
    __syncthreads();

    // ---------------- Phase D: ctx2 = ctx @ Wo^T + bo -> SQ ----------------
    {
        const float* WoT = g_WT[3];
        if (tid < DD) {
            const int d = tid;
            const float bbo = bo[d];
            for (int lh = 0; lh < 2; ++lh) {
                float ac[16];
                #pragma unroll
                for (int u = 0; u < 16; ++u) ac[u] = 0.f;
                const float* xb = SX + lh * 16 * DD;
                #pragma unroll 4
                for (int kk = 0; kk < DD; ++kk) {
                    float w = WoT[kk * DD + d];
                    #pragma unroll
                    for (int u = 0; u < 16; ++u)
                        ac[u] = fmaf(xb[u * DD + kk], w, ac[u]);
                }
                #pragma unroll
                for (int u = 0; u < 16; ++u)
                    SQ[(lh * 16 + u) * DD + d] = ac[u] + bbo;
            }
        }
    }
    __syncthreads();

    // ---------------- Phase E1: t = tanh(ctx2 @ Va^T + ba) -> SK ----------------
    {
        const float* VaT = g_WT[4];
        if (tid < DD) {
            const int d = tid;
            const float bba = ba[d];
            for (int lh = 0; lh < 2; ++lh) {
                float ac[16];
                #pragma unroll
                for (int u = 0; u < 16; ++u) ac[u] = 0.f;
                const float* xb = SQ + lh * 16 * DD;
                #pragma unroll 4
                for (int kk = 0; kk < DD; ++kk) {
                    float w = VaT[kk * DD + d];
                    #pragma unroll
                    for (int u = 0; u < 16; ++u)
                        ac[u] = fmaf(xb[u * DD + kk], w, ac[u]);
                }
                #pragma unroll
                for (int u = 0; u < 16; ++u)
                    SK[(lh * 16 + u) * DD + d] = tanhf(ac[u] + bba);
            }
        }
    }
    __syncthreads();

    // ---------------- Phase E2: pooling ----------------
    {
        const int wid  = tid >> 5;
        const int lane = tid & 31;
        for (int l = wid; l < LL; l += NT / 32) {
            float p = 0.f;
            for (int dd2 = lane; dd2 < DD; dd2 += 32)
                p = fmaf(SK[l * DD + dd2], qw[dd2], p);
            #pragma unroll
            for (int o = 16; o; o >>= 1) p += __shfl_xor_sync(0xffffffffu, p, o);
            if (lane == 0) SA[l] = p;
        }
        __syncthreads();
        if (wid == 0) {
            float v = SA[lane];        // L == 32
            float m = v;
            #pragma unroll
            for (int o = 16; o; o >>= 1)
                m = fmaxf(m, __shfl_xor_sync(0xffffffffu, m, o));
            float e = __expf(v - m);
            float sum = e;
            #pragma unroll
            for (int o = 16; o; o >>= 1)
                sum += __shfl_xor_sync(0xffffffffu, sum, o);
            SAL[lane] = e / sum;
        }
        __syncthreads();
        if (tid < DD) {
            float o = 0.f;
            #pragma unroll
            for (int l = 0; l < LL; ++l)
                o = fmaf(SAL[l], SQ[l * DD + tid], o);
            out[(size_t)b * DD + tid] = o;
        }
    }
}

extern "C" void kernel_launch(void* const* d_in, const int* in_sizes, int n_in,
                              void* d_out, int out_size) {
    const int*   title = (const int*)  d_in[0];
    const float* emb   = (const float*)d_in[1];
    const float* pos   = (const float*)d_in[2];
    const float* Wq    = (const float*)d_in[3];
    const float* bq    = (const float*)d_in[4];
    const float* Wk    = (const float*)d_in[5];
    const float* bk    = (const float*)d_in[6];
    const float* Wv    = (const float*)d_in[7];
    const float* bv    = (const float*)d_in[8];
    const float* Wo    = (const float*)d_in[9];
    const float* bo    = (const float*)d_in[10];
    const float* Va    = (const float*)d_in[11];
    const float* ba    = (const float*)d_in[12];
    const float* qw    = (const float*)d_in[13];
    float* out = (float*)d_out;

    size_t shbytes = (size_t)(4 * LL * DD + 64) * sizeof(float) + 32 * sizeof(int);
    cudaFuncSetAttribute(encoder_kernel,
                         cudaFuncAttributeMaxDynamicSharedMemorySize,
                         (int)shbytes);

    dim3 tgrid(64, 5);
    transpose_kernel<<<tgrid, 256>>>(Wq, Wk, Wv, Wo, Va);

    encoder_kernel<<<BB, NT, shbytes>>>(title, emb, pos,
                                        bq, bk, bv, bo, ba, qw, out);
}

// round 3
// speedup vs baseline: 2.4611x; 2.4611x over previous
#include <cuda_runtime.h>
#include <math.h>

#define BB 4096
#define LL 32
#define DD 300
#define HH 6
#define HDD 50
#define NT 608          // 19 warps
#define NW 19
#define KP 304          // padded K/N (38 chunks of 8)
#define XS 308          // smem row stride in floats -> conflict-free frag loads
#define NKC (KP / 8)    // 38 k-chunks

// tf32-rounded, zero-padded weights: g_Wr[m][n*KP + k] = rna_tf32(W[n*DD + k])
__device__ float g_Wr[5][KP * KP];

__device__ __forceinline__ float tf32r(float x) {
    unsigned r;
    asm("cvt.rna.tf32.f32 %0, %1;" : "=r"(r) : "f"(x));
    return __uint_as_float(r);
}

__global__ void prep_kernel(const float* __restrict__ Wq, const float* __restrict__ Wk,
                            const float* __restrict__ Wv, const float* __restrict__ Wo,
                            const float* __restrict__ Va) {
    const float* src;
    int m = blockIdx.y;
    switch (m) {
        case 0: src = Wq; break;
        case 1: src = Wk; break;
        case 2: src = Wv; break;
        case 3: src = Wo; break;
        default: src = Va; break;
    }
    float* dst = g_Wr[m];
    for (int idx = blockIdx.x * blockDim.x + threadIdx.x; idx < KP * KP;
         idx += gridDim.x * blockDim.x) {
        int n = idx / KP, k = idx - n * KP;
        dst[idx] = (n < DD && k < DD) ? tf32r(src[n * DD + k]) : 0.f;
    }
}

// D += A(16x8 row) * B(8x8 col);  C/D fp32, A/B tf32 bit-patterns in fp32 regs
__device__ __forceinline__ void mma8(float c[4], const float a[4], float b0, float b1) {
    asm volatile(
        "mma.sync.aligned.m16n8k8.row.col.f32.tf32.tf32.f32 "
        "{%0,%1,%2,%3},{%4,%5,%6,%7},{%8,%9},{%0,%1,%2,%3};"
        : "+f"(c[0]), "+f"(c[1]), "+f"(c[2]), "+f"(c[3])
        : "r"(__float_as_uint(a[0])), "r"(__float_as_uint(a[1])),
          "r"(__float_as_uint(a[2])), "r"(__float_as_uint(a[3])),
          "r"(__float_as_uint(b0)), "r"(__float_as_uint(b1)));
}

// One [32 x 300] x [300 x 300] GEMM: warp `wid` owns 16 output columns.
__device__ __forceinline__ void gemm16(const float* __restrict__ S,    // src [32][XS]
                                       const float* __restrict__ Wg,   // [KP*KP]
                                       const float* __restrict__ bias,
                                       float* __restrict__ Dst,        // [32][XS]
                                       int wid, int gid, int ctg, bool dotanh) {
    const int n0 = wid * 16;
    float c[2][2][4] = {};
    for (int kc = 0; kc < NKC; ++kc) {
        const int k0 = kc * 8;
        float a[2][4];
        #pragma unroll
        for (int m = 0; m < 2; ++m) {
            const float* xr = S + (m * 16 + gid) * XS + k0;
            a[m][0] = xr[ctg];
            a[m][1] = xr[8 * XS + ctg];
            a[m][2] = xr[ctg + 4];
            a[m][3] = xr[8 * XS + ctg + 4];
        }
        #pragma unroll
        for (int t = 0; t < 2; ++t) {
            const float* wr = Wg + (n0 + t * 8 + gid) * KP + k0;
            float b0 = wr[ctg], b1 = wr[ctg + 4];
            #pragma unroll
            for (int m = 0; m < 2; ++m) mma8(c[t][m], a[m], b0, b1);
        }
    }
    #pragma unroll
    for (int t = 0; t < 2; ++t)
        #pragma unroll
        for (int m = 0; m < 2; ++m)
            #pragma unroll
            for (int i = 0; i < 4; ++i) {
                int n = n0 + t * 8 + 2 * ctg + (i & 1);
                int r = m * 16 + gid + (i >> 1) * 8;
                if (n < DD) {
                    float v = c[t][m][i] + bias[n];
                    if (dotanh) v = tanhf(v);
                    Dst[r * XS + n] = v;
                }
            }
}

__global__ __launch_bounds__(NT, 1)
void encoder_kernel(const int* __restrict__ title,
                    const float* __restrict__ emb,
                    const float* __restrict__ pos,
                    const float* __restrict__ bq,
                    const float* __restrict__ bk,
                    const float* __restrict__ bv,
                    const float* __restrict__ bo,
                    const float* __restrict__ ba,
                    const float* __restrict__ qw,
                    float* __restrict__ out) {
    extern __shared__ float sm[];
    float* SX  = sm;                 // x -> ctx
    float* SQ  = sm + 1 * LL * XS;   // q -> ctx2
    float* SK  = sm + 2 * LL * XS;   // k -> t
    float* SV  = sm + 3 * LL * XS;   // v
    float* SA  = sm + 4 * LL * XS;
    float* SAL = SA + 32;
    int*   STL = (int*)(SAL + 32);

    const int b    = blockIdx.x;
    const int tid  = threadIdx.x;
    const int wid  = tid >> 5;
    const int lane = tid & 31;
    const int gid  = lane >> 2;   // 0..7
    const int ctg  = lane & 3;    // 0..3

    if (tid < LL) STL[tid] = title[b * LL + tid];
    __syncthreads();

    // ---------------- Phase A: x = tf32(emb[title] + pos), zero pads ----------------
    for (int idx = tid; idx < LL * XS; idx += NT) {
        int l = idx / XS, d = idx - l * XS;
        float v = 0.f;
        if (d < DD) v = tf32r(emb[(size_t)STL[l] * DD + d] + pos[l * DD + d]);
        SX[idx] = v;
        if (d >= DD) { SQ[idx] = 0.f; SK[idx] = 0.f; SV[idx] = 0.f; }
    }
    __syncthreads();

    // ---------------- Phase B: fused QKV via tf32 HMMA ----------------
    {
        const int n0 = wid * 16;
        float c[3][2][2][4] = {};
        for (int kc = 0; kc < NKC; ++kc) {
            const int k0 = kc * 8;
            float a[2][4];
            #pragma unroll
            for (int m = 0; m < 2; ++m) {
                const float* xr = SX + (m * 16 + gid) * XS + k0;
                a[m][0] = xr[ctg];
                a[m][1] = xr[8 * XS + ctg];
                a[m][2] = xr[ctg + 4];
                a[m][3] = xr[8 * XS + ctg + 4];
            }
            #pragma unroll
            for (int g = 0; g < 3; ++g) {
                #pragma unroll
                for (int t = 0; t < 2; ++t) {
                    const float* wr = g_Wr[g] + (n0 + t * 8 + gid) * KP + k0;
                    float b0 = wr[ctg], b1 = wr[ctg + 4];
                    #pragma unroll
                    for (int m = 0; m < 2; ++m) mma8(c[g][t][m], a[m], b0, b1);
                }
            }
        }
        const float rs = rsqrtf((float)HDD);
        #pragma unroll
        for (int t = 0; t < 2; ++t)
            #pragma unroll
            for (int m = 0; m < 2; ++m)
                #pragma unroll
                for (int i = 0; i < 4; ++i) {
                    int n = n0 + t * 8 + 2 * ctg + (i & 1);
                    int r = m * 16 + gid + (i >> 1) * 8;
                    if (n < DD) {
                        SQ[r * XS + n] = (c[0][t][m][i] + bq[n]) * rs;
                        SK[r * XS + n] = c[1][t][m][i] + bk[n];
                        SV[r * XS + n] = c[2][t][m][i] + bv[n];
                    }
                }
    }
    __syncthreads();

    // ---------------- Phase C: attention (scalar fp32), ctx -> SX ----------------
    if (tid < HH * LL) {
        const int h = tid >> 5;       // warp == head
        const int i = tid & 31;       // lane == query row
        const int off = h * HDD;
        float s[LL];
        #pragma unroll
        for (int j = 0; j < LL; ++j) s[j] = 0.f;
        for (int hd = 0; hd < HDD; ++hd) {
            float qv = SQ[i * XS + off + hd];
            #pragma unroll
            for (int j = 0; j < LL; ++j)
                s[j] = fmaf(qv, SK[j * XS + off + hd], s[j]);
        }
        float m = -1e30f;
        #pragma unroll
        for (int j = 0; j < LL; ++j) m = fmaxf(m, s[j]);
        float sum = 0.f;
        #pragma unroll
        for (int j = 0; j < LL; ++j) { s[j] = __expf(s[j] - m); sum += s[j]; }
        float inv = 1.f / sum;
        #pragma unroll
        for (int j = 0; j < LL; ++j) s[j] *= inv;
        for (int hd = 0; hd < HDD; ++hd) {
            float cx = 0.f;
            #pragma unroll
            for (int j = 0; j < LL; ++j)
                cx = fmaf(s[j], SV[j * XS + off + hd], cx);
            SX[i * XS + off + hd] = tf32r(cx);   // rna-rounded for next GEMM
        }
    }
    __syncthreads();

    // ---------------- Phase D: ctx2 = ctx @ Wo^T + bo  -> SQ ----------------
    gemm16(SX, g_Wr[3], bo, SQ, wid, gid, ctg, false);
    __syncthreads();

    // ---------------- Phase E1: t = tanh(ctx2 @ Va^T + ba) -> SK ----------------
    gemm16(SQ, g_Wr[4], ba, SK, wid, gid, ctg, true);
    __syncthreads();

    // ---------------- Phase E2: additive attention pooling ----------------
    for (int l = wid; l < LL; l += NW) {
        float p = 0.f;
        for (int d2 = lane; d2 < DD; d2 += 32)
            p = fmaf(SK[l * XS + d2], qw[d2], p);
        #pragma unroll
        for (int o = 16; o; o >>= 1) p += __shfl_xor_sync(0xffffffffu, p, o);
        if (lane == 0) SA[l] = p;
    }
    __syncthreads();
    if (wid == 0) {
        float v = SA[lane];
        float m = v;
        #pragma unroll
        for (int o = 16; o; o >>= 1) m = fmaxf(m, __shfl_xor_sync(0xffffffffu, m, o));
        float e = __expf(v - m);
        float sum = e;
        #pragma unroll
        for (int o = 16; o; o >>= 1) sum += __shfl_xor_sync(0xffffffffu, sum, o);
        SAL[lane] = e / sum;
    }
    __syncthreads();
    if (tid < DD) {
        float o = 0.f;
        #pragma unroll
        for (int l = 0; l < LL; ++l)
            o = fmaf(SAL[l], SQ[l * XS + tid], o);
        out[(size_t)b * DD + tid] = o;
    }
}

extern "C" void kernel_launch(void* const* d_in, const int* in_sizes, int n_in,
                              void* d_out, int out_size) {
    const int*   title = (const int*)  d_in[0];
    const float* emb   = (const float*)d_in[1];
    const float* pos   = (const float*)d_in[2];
    const float* Wq    = (const float*)d_in[3];
    const float* bq    = (const float*)d_in[4];
    const float* Wk    = (const float*)d_in[5];
    const float* bk    = (const float*)d_in[6];
    const float* Wv    = (const float*)d_in[7];
    const float* bv    = (const float*)d_in[8];
    const float* Wo    = (const float*)d_in[9];
    const float* bo    = (const float*)d_in[10];
    const float* Va    = (const float*)d_in[11];
    const float* ba    = (const float*)d_in[12];
    const float* qw    = (const float*)d_in[13];
    float* out = (float*)d_out;

    size_t shbytes = (size_t)(4 * LL * XS + 64) * sizeof(float) + 32 * sizeof(int);
    cudaFuncSetAttribute(encoder_kernel,
                         cudaFuncAttributeMaxDynamicSharedMemorySize,
                         (int)shbytes);

    dim3 pgrid(64, 5);
    prep_kernel<<<pgrid, 256>>>(Wq, Wk, Wv, Wo, Va);

    encoder_kernel<<<BB, NT, shbytes>>>(title, emb, pos,
                                        bq, bk, bv, bo, ba, qw, out);
}